// round 4
// baseline (speedup 1.0000x reference)
#include <cuda_runtime.h>
#include <math.h>

// ---------------- problem dims ----------------
#define T_STEPS   128
#define IN_DIM    512
#define C_INT     8
#define ISQ       16
#define DIMN      256
#define NCH       8
#define OUT_CH    16
#define EMB_OUT   2048          // C_INT*ISQ*ISQ

// ---------------- scratch (static device globals; no allocs) ----------------
__device__ float g_WT[IN_DIM * EMB_OUT];       // W_embed transposed: [k][o]
__device__ float g_v[T_STEPS * EMB_OUT];       // masked coarse activations
__device__ float g_Z[2][NCH * DIMN * DIMN];    // ping-pong reservoir state

// ---------------- W_embed transpose (tiled, conflict-free) ----------------
__global__ void k_transpose(const float* __restrict__ W) {
    __shared__ float tile[32][33];
    int ob = blockIdx.x * 32;           // o tile (2048/32 = 64)
    int kb = blockIdx.y * 32;           // k tile (512/32 = 16)
    int tx = threadIdx.x, ty = threadIdx.y;
#pragma unroll
    for (int i = 0; i < 4; i++)
        tile[ty + 8 * i][tx] = W[(ob + ty + 8 * i) * IN_DIM + kb + tx];
    __syncthreads();
#pragma unroll
    for (int i = 0; i < 4; i++)
        g_WT[(kb + ty + 8 * i) * EMB_OUT + ob + tx] = tile[tx][ty + 8 * i];
}

// ---------------- embed GEMM: v[t][o] = (X[t,:]·W[o,:]) * mask_coarse ------
// block = 16 t  x 256 o; thread owns 4t x 4o.
__global__ __launch_bounds__(256) void k_embed(const float* __restrict__ X,
                                               const float* __restrict__ maskc) {
    __shared__ float sX[16 * IN_DIM];   // 32 KB
    int tt0 = blockIdx.x * 16;
    int ob  = blockIdx.y * 256;
    for (int idx = threadIdx.x; idx < 16 * IN_DIM; idx += 256)
        sX[idx] = X[(tt0 + (idx >> 9)) * IN_DIM + (idx & 511)];
    __syncthreads();

    int to = threadIdx.x & 63;          // o lane (coalesced W loads)
    int tg = threadIdx.x >> 6;          // t group 0..3
    float acc[4][4];
#pragma unroll
    for (int a = 0; a < 4; a++)
#pragma unroll
        for (int b = 0; b < 4; b++) acc[a][b] = 0.f;

    for (int k = 0; k < IN_DIM; k++) {
        float w[4];
#pragma unroll
        for (int oi = 0; oi < 4; oi++)
            w[oi] = g_WT[k * EMB_OUT + ob + to + 64 * oi];
#pragma unroll
        for (int ti = 0; ti < 4; ti++) {
            float xv = sX[(tg * 4 + ti) * IN_DIM + k];
#pragma unroll
            for (int oi = 0; oi < 4; oi++) acc[ti][oi] += xv * w[oi];
        }
    }
#pragma unroll
    for (int ti = 0; ti < 4; ti++)
#pragma unroll
        for (int oi = 0; oi < 4; oi++) {
            int t = tt0 + tg * 4 + ti;
            int o = ob + to + 64 * oi;
            g_v[t * EMB_OUT + o] = acc[ti][oi] * maskc[o & 255];
        }
}

// ---------------- init output with bias (d_out is poisoned) ----------------
__global__ void k_init_out(float* __restrict__ y, const float* __restrict__ b) {
    int idx = blockIdx.x * 256 + threadIdx.x;
    if (idx < T_STEPS * 1024) y[idx] = b[(idx >> 6) & 15];
}

// ---------------- zero initial state ----------------
__global__ void k_zero() {
    int idx = blockIdx.x * 256 + threadIdx.x;
    if (idx < NCH * DIMN * DIMN) g_Z[0][idx] = 0.f;
}

// ---------------- one reservoir step + fused readout ----------------
// grid = 256 blocks: block b -> channel c = b>>5, row group r0 = (b&31)*8
// thread = column x (0..255); processes 8 rows.
__global__ __launch_bounds__(256) void k_step(int t,
    const float* __restrict__ maskf, const float* __restrict__ Wd,
    const float* __restrict__ w1g,  const float* __restrict__ w2g,
    const float* __restrict__ wog,  float* __restrict__ yout)
{
    const int p = t & 1;
    const float* __restrict__ Zold = g_Z[p];
    float* __restrict__ Znew = g_Z[p ^ 1];

    const int c  = blockIdx.x >> 5;
    const int r0 = (blockIdx.x & 31) << 3;
    const int tid = threadIdx.x;

    __shared__ float s_tile[16][264];    // rows r0-4..r0+11, cols -4..259 (wrapped)
    __shared__ float s_wdec[8 * 256];    // W_deconv[ci][c][a][b]
    __shared__ float s_wout[16 * 256];   // w_out[oc][c][(r0%32)+r][b]
    __shared__ float s_v[2][8][16];      // v for i = r0/16 and (r0+7)/16

    const float* Zc = Zold + c * (DIMN * DIMN);
    for (int idx = tid; idx < 16 * 264; idx += 256) {
        int rr = idx / 264, sc = idx - rr * 264;
        int gr = (r0 - 4 + rr) & 255;
        int gc = (sc - 4) & 255;
        s_tile[rr][sc] = Zc[gr * 256 + gc];
    }
    for (int idx = tid; idx < 2048; idx += 256) {
        int ci = idx >> 8;
        s_wdec[idx] = Wd[ci * 2048 + c * 256 + (idx & 255)];
    }
    for (int idx = tid; idx < 4096; idx += 256) {
        int oc = idx >> 8;
        int rb = idx & 255;
        int rr = rb >> 5, bb = rb & 31;
        int a  = (r0 & 31) + rr;
        s_wout[idx] = wog[oc * 8192 + c * 1024 + a * 32 + bb];
    }
    {
        const int i_lo = r0 >> 4, i_hi = (r0 + 7) >> 4;
        int ii = tid >> 7, ci = (tid >> 4) & 7, j = tid & 15;
        int i  = ii ? i_hi : i_lo;
        s_v[ii][ci][j] = g_v[t * EMB_OUT + ci * 256 + i * 16 + j];
    }
    float w1[9], w2[25];
#pragma unroll
    for (int i = 0; i < 9; i++)  w1[i] = w1g[c * 9 + i];
#pragma unroll
    for (int i = 0; i < 25; i++) w2[i] = w2g[c * 25 + i];
    __syncthreads();

    const int x   = tid;
    const int jv  = x >> 4;       // coarse j
    const int b16 = x & 15;       // deconv col
    const int xl  = x & 31;       // readout col
    const int i_lo = r0 >> 4;

    float acc[16];
#pragma unroll
    for (int i = 0; i < 16; i++) acc[i] = 0.f;

#pragma unroll
    for (int r = 0; r < 8; r++) {
        const int yrow = r0 + r;
        const int srow = r + 4;
        const int sc   = x + 4;

        float c1 = 0.f;
#pragma unroll
        for (int a = 0; a < 3; a++)
#pragma unroll
            for (int bb = 0; bb < 3; bb++)
                c1 += s_tile[srow - 1 + a][sc - 1 + bb] * w1[a * 3 + bb];

        float c2 = 0.f;
#pragma unroll
        for (int a = 0; a < 5; a++)
#pragma unroll
            for (int bb = 0; bb < 5; bb++)
                c2 += s_tile[srow - 4 + 2 * a][sc - 4 + 2 * bb] * w2[a * 5 + bb];

        // on-the-fly deconv input u
        const int ii  = (yrow >> 4) - i_lo;   // 0 or 1
        const int a16 = yrow & 15;
        float uv = 0.f;
#pragma unroll
        for (int ci = 0; ci < 8; ci++)
            uv += s_v[ii][ci][jv] * s_wdec[ci * 256 + a16 * 16 + b16];
        uv *= maskf[yrow * 256 + x];

        const float z = tanhf(0.9f * c1 + 0.1f * c2 + uv);
        Znew[c * 65536 + yrow * 256 + x] = z;

#pragma unroll
        for (int oc = 0; oc < 16; oc++)
            acc[oc] += z * s_wout[oc * 256 + r * 32 + xl];
    }

    // warp-level readout reduction: each warp == one 32-col j band
#pragma unroll
    for (int oc = 0; oc < 16; oc++) {
        float v = acc[oc];
        v += __shfl_xor_sync(0xffffffffu, v, 16);
        v += __shfl_xor_sync(0xffffffffu, v, 8);
        v += __shfl_xor_sync(0xffffffffu, v, 4);
        v += __shfl_xor_sync(0xffffffffu, v, 2);
        v += __shfl_xor_sync(0xffffffffu, v, 1);
        if ((tid & 31) == 0) {
            const int iy = r0 >> 5;
            const int jw = tid >> 5;
            atomicAdd(&yout[t * 1024 + oc * 64 + iy * 8 + jw], v);
        }
    }
}

// ---------------- launcher (graph-capturable, alloc-free) ----------------
extern "C" void kernel_launch(void* const* d_in, const int* in_sizes, int n_in,
                              void* d_out, int out_size)
{
    const float* X           = (const float*)d_in[0];  // [128,512]
    const float* W_embed     = (const float*)d_in[1];  // [2048,512]
    const float* mask_coarse = (const float*)d_in[2];  // [16,16]
    const float* mask_fine   = (const float*)d_in[3];  // [256,256]
    const float* W_deconv    = (const float*)d_in[4];  // [8,8,16,16]
    const float* w1          = (const float*)d_in[5];  // [8,1,3,3]
    const float* w2          = (const float*)d_in[6];  // [8,1,5,5]
    const float* w_out       = (const float*)d_in[7];  // [16,8,32,32]
    const float* b_out       = (const float*)d_in[8];  // [16]
    float* y = (float*)d_out;                          // [128,1024]

    k_transpose<<<dim3(64, 16), dim3(32, 8)>>>(W_embed);
    k_embed<<<dim3(8, 8), 256>>>(X, mask_coarse);
    k_init_out<<<512, 256>>>(y, b_out);
    k_zero<<<2048, 256>>>();
    for (int t = 0; t < T_STEPS; t++)
        k_step<<<256, 256>>>(t, mask_fine, W_deconv, w1, w2, w_out, y);
}

// round 5
// speedup vs baseline: 2.3030x; 2.3030x over previous
#include <cuda_runtime.h>
#include <math.h>

// ---------------- problem dims ----------------
#define T_STEPS   128
#define IN_DIM    512
#define C_INT     8
#define ISQ       16
#define DIMN      256
#define NCH       8
#define OUT_CH    16
#define EMB_OUT   2048          // C_INT*ISQ*ISQ

// ---------------- scratch (static device globals; no allocs) ----------------
__device__ float g_WT[IN_DIM * EMB_OUT];       // W_embed transposed: [k][o]
__device__ float g_v[T_STEPS * EMB_OUT];       // masked coarse activations
__device__ float g_Z[2][NCH * DIMN * DIMN];    // ping-pong reservoir state
__device__ unsigned g_barcnt;                  // grid barrier counter

// ---------------- W_embed transpose (tiled, conflict-free) ----------------
__global__ void k_transpose(const float* __restrict__ W) {
    __shared__ float tile[32][33];
    int ob = blockIdx.x * 32;
    int kb = blockIdx.y * 32;
    int tx = threadIdx.x, ty = threadIdx.y;
#pragma unroll
    for (int i = 0; i < 4; i++)
        tile[ty + 8 * i][tx] = W[(ob + ty + 8 * i) * IN_DIM + kb + tx];
    __syncthreads();
#pragma unroll
    for (int i = 0; i < 4; i++)
        g_WT[(kb + ty + 8 * i) * EMB_OUT + ob + tx] = tile[tx][ty + 8 * i];
}

// ---------------- embed GEMM: v[t][o] = (X[t,:]·W[o,:]) * mask_coarse ------
__global__ __launch_bounds__(256) void k_embed(const float* __restrict__ X,
                                               const float* __restrict__ maskc) {
    __shared__ float sX[16 * IN_DIM];
    int tt0 = blockIdx.x * 16;
    int ob  = blockIdx.y * 256;
    for (int idx = threadIdx.x; idx < 16 * IN_DIM; idx += 256)
        sX[idx] = X[(tt0 + (idx >> 9)) * IN_DIM + (idx & 511)];
    __syncthreads();

    int to = threadIdx.x & 63;
    int tg = threadIdx.x >> 6;
    float acc[4][4];
#pragma unroll
    for (int a = 0; a < 4; a++)
#pragma unroll
        for (int b = 0; b < 4; b++) acc[a][b] = 0.f;

    for (int k = 0; k < IN_DIM; k++) {
        float w[4];
#pragma unroll
        for (int oi = 0; oi < 4; oi++)
            w[oi] = g_WT[k * EMB_OUT + ob + to + 64 * oi];
#pragma unroll
        for (int ti = 0; ti < 4; ti++) {
            float xv = sX[(tg * 4 + ti) * IN_DIM + k];
#pragma unroll
            for (int oi = 0; oi < 4; oi++) acc[ti][oi] += xv * w[oi];
        }
    }
#pragma unroll
    for (int ti = 0; ti < 4; ti++)
#pragma unroll
        for (int oi = 0; oi < 4; oi++) {
            int t = tt0 + tg * 4 + ti;
            int o = ob + to + 64 * oi;
            g_v[t * EMB_OUT + o] = acc[ti][oi] * maskc[o & 255];
        }
}

// ---------------- init output with bias (d_out is poisoned) ----------------
__global__ void k_init_out(float* __restrict__ y, const float* __restrict__ b) {
    int idx = blockIdx.x * 256 + threadIdx.x;
    if (idx < T_STEPS * 1024) y[idx] = b[(idx >> 6) & 15];
}

// ---------------- zero initial state + barrier counter ----------------
__global__ void k_zero() {
    int idx = blockIdx.x * 256 + threadIdx.x;
    if (idx == 0) g_barcnt = 0u;
    if (idx < NCH * DIMN * DIMN) g_Z[0][idx] = 0.f;
}

// ---------------- persistent reservoir scan + fused readout ----------------
// grid = 256 blocks resident (2/SM): block b -> channel c = b>>5, rows r0..r0+7
// thread = column x (0..255)
__global__ __launch_bounds__(256, 2) void k_scan(
    const float* __restrict__ maskf, const float* __restrict__ Wd,
    const float* __restrict__ w1g,  const float* __restrict__ w2g,
    const float* __restrict__ wog,  float* __restrict__ yout)
{
    const int c   = blockIdx.x >> 5;
    const int r0  = (blockIdx.x & 31) << 3;
    const int tid = threadIdx.x;
    const int x   = tid;

    __shared__ __align__(16) float s_tile[16][264];    // 16.9 KB
    __shared__ __align__(16) float s_wdecT[8 * 16 * 8]; // [al][b16][ci]  4 KB
    __shared__ __align__(16) float s_woutT[32 * 140];   // [xl][r*16+oc] 17.9 KB

    // ---- one-time weight staging ----
    const int a0 = r0 & 15;   // 0 or 8: base fine-row within deconv kernel
    for (int idx = tid; idx < 1024; idx += 256) {
        int ci = idx & 7, b16 = (idx >> 3) & 15, al = idx >> 7;
        s_wdecT[idx] = Wd[ci * 2048 + c * 256 + (a0 + al) * 16 + b16];
    }
    for (int idx = tid; idx < 4096; idx += 256) {
        int oc = idx & 15, r = (idx >> 4) & 7, xl2 = idx >> 7;
        s_woutT[xl2 * 140 + r * 16 + oc] =
            wog[oc * 8192 + c * 1024 + ((r0 & 31) + r) * 32 + xl2];
    }
    float w1[9], w2[25], maskreg[8];
#pragma unroll
    for (int i = 0; i < 9; i++)  w1[i] = 0.9f * w1g[c * 9 + i];
#pragma unroll
    for (int i = 0; i < 25; i++) w2[i] = 0.1f * w2g[c * 25 + i];
#pragma unroll
    for (int r = 0; r < 8; r++)  maskreg[r] = maskf[(r0 + r) * 256 + x];

    const int jv = x >> 4;        // coarse j (0..15)
    const int b16 = x & 15;       // deconv col
    const int xl = x & 31;        // readout col within 32-band
    const int iy = r0 >> 5;       // readout spatial row
    const int jw = x >> 5;        // readout spatial col (warp id)
    const int ic = r0 >> 4;       // coarse i (constant for block)
    const int sc = x + 4;

    __syncthreads();

    for (int t = 0; t < T_STEPS; t++) {
        const float* __restrict__ Zc   = g_Z[t & 1] + c * 65536;
        float* __restrict__       Znew = g_Z[(t & 1) ^ 1] + c * 65536;

        // stage state tile (L2-coherent loads; rows r0-4..r0+11, cols -4..259)
        for (int idx = tid; idx < 16 * 264; idx += 256) {
            int rr = idx / 264, sc2 = idx - rr * 264;
            int gr = (r0 - 4 + rr) & 255;
            int gc = (sc2 - 4) & 255;
            s_tile[rr][sc2] = __ldcg(&Zc[gr * 256 + gc]);
        }
        float vr[8];
#pragma unroll
        for (int ci = 0; ci < 8; ci++)
            vr[ci] = __ldg(&g_v[t * EMB_OUT + ci * 256 + ic * 16 + jv]);
        __syncthreads();

        // ---- rolling depthwise convs: each tile row loaded once ----
        float acc[8];
#pragma unroll
        for (int r = 0; r < 8; r++) acc[r] = 0.f;

#pragma unroll
        for (int rr = 0; rr < 16; rr++) {
            float t0 = s_tile[rr][sc - 4];
            float t1 = s_tile[rr][sc - 2];
            float t2 = s_tile[rr][sc];
            float t3 = s_tile[rr][sc + 2];
            float t4 = s_tile[rr][sc + 4];
#pragma unroll
            for (int a = 0; a < 5; a++) {
                int r = rr - 2 * a;
                if (r >= 0 && r < 8)
                    acc[r] += t0 * w2[a * 5 + 0] + t1 * w2[a * 5 + 1]
                            + t2 * w2[a * 5 + 2] + t3 * w2[a * 5 + 3]
                            + t4 * w2[a * 5 + 4];
            }
            if (rr >= 3 && rr <= 12) {
                float u0 = s_tile[rr][sc - 1];
                float u2 = s_tile[rr][sc + 1];
#pragma unroll
                for (int a = 0; a < 3; a++) {
                    int r = rr - 3 - a;
                    if (r >= 0 && r < 8)
                        acc[r] += u0 * w1[a * 3 + 0] + t2 * w1[a * 3 + 1]
                                + u2 * w1[a * 3 + 2];
                }
            }
        }

        // ---- per-row: deconv input, tanh, state store, readout ----
        float accro[16];
#pragma unroll
        for (int oc = 0; oc < 16; oc++) accro[oc] = 0.f;

#pragma unroll
        for (int r = 0; r < 8; r++) {
            const float4 wA = *(const float4*)&s_wdecT[r * 128 + b16 * 8];
            const float4 wB = *(const float4*)&s_wdecT[r * 128 + b16 * 8 + 4];
            float uv = vr[0] * wA.x + vr[1] * wA.y + vr[2] * wA.z + vr[3] * wA.w
                     + vr[4] * wB.x + vr[5] * wB.y + vr[6] * wB.z + vr[7] * wB.w;

            float z = tanhf(acc[r] + uv * maskreg[r]);
            __stcg(&Znew[(r0 + r) * 256 + x], z);

            const float4 o0 = *(const float4*)&s_woutT[xl * 140 + r * 16 + 0];
            const float4 o1 = *(const float4*)&s_woutT[xl * 140 + r * 16 + 4];
            const float4 o2 = *(const float4*)&s_woutT[xl * 140 + r * 16 + 8];
            const float4 o3 = *(const float4*)&s_woutT[xl * 140 + r * 16 + 12];
            accro[0]  += z * o0.x;  accro[1]  += z * o0.y;
            accro[2]  += z * o0.z;  accro[3]  += z * o0.w;
            accro[4]  += z * o1.x;  accro[5]  += z * o1.y;
            accro[6]  += z * o1.z;  accro[7]  += z * o1.w;
            accro[8]  += z * o2.x;  accro[9]  += z * o2.y;
            accro[10] += z * o2.z;  accro[11] += z * o2.w;
            accro[12] += z * o3.x;  accro[13] += z * o3.y;
            accro[14] += z * o3.z;  accro[15] += z * o3.w;
        }

        // warp-level readout reduction (one 32-col band per warp)
#pragma unroll
        for (int oc = 0; oc < 16; oc++) {
            float v = accro[oc];
            v += __shfl_xor_sync(0xffffffffu, v, 16);
            v += __shfl_xor_sync(0xffffffffu, v, 8);
            v += __shfl_xor_sync(0xffffffffu, v, 4);
            v += __shfl_xor_sync(0xffffffffu, v, 2);
            v += __shfl_xor_sync(0xffffffffu, v, 1);
            if ((x & 31) == 0)
                atomicAdd(&yout[t * 1024 + oc * 64 + iy * 8 + jw], v);
        }

        // ---- grid-wide barrier (skip after last step) ----
        __syncthreads();                 // all reads of s_tile / writes done
        if (t < T_STEPS - 1) {
            if (tid == 0) {
                __threadfence();         // release this block's Z stores
                atomicAdd(&g_barcnt, 1u);
                const unsigned target = (unsigned)(t + 1) * 256u;
                volatile unsigned* p = &g_barcnt;
                while (*p < target) __nanosleep(64);
                __threadfence();         // acquire other blocks' Z stores
            }
            __syncthreads();
        }
    }
}

// ---------------- launcher (graph-capturable, alloc-free) ----------------
extern "C" void kernel_launch(void* const* d_in, const int* in_sizes, int n_in,
                              void* d_out, int out_size)
{
    const float* X           = (const float*)d_in[0];  // [128,512]
    const float* W_embed     = (const float*)d_in[1];  // [2048,512]
    const float* mask_coarse = (const float*)d_in[2];  // [16,16]
    const float* mask_fine   = (const float*)d_in[3];  // [256,256]
    const float* W_deconv    = (const float*)d_in[4];  // [8,8,16,16]
    const float* w1          = (const float*)d_in[5];  // [8,1,3,3]
    const float* w2          = (const float*)d_in[6];  // [8,1,5,5]
    const float* w_out       = (const float*)d_in[7];  // [16,8,32,32]
    const float* b_out       = (const float*)d_in[8];  // [16]
    float* y = (float*)d_out;                          // [128,1024]

    k_transpose<<<dim3(64, 16), dim3(32, 8)>>>(W_embed);
    k_embed<<<dim3(8, 8), 256>>>(X, mask_coarse);
    k_init_out<<<512, 256>>>(y, b_out);
    k_zero<<<2048, 256>>>();
    k_scan<<<256, 256>>>(mask_fine, W_deconv, w1, w2, w_out, y);
}

// round 6
// speedup vs baseline: 2.8410x; 1.2336x over previous
#include <cuda_runtime.h>
#include <math.h>

// ---------------- problem dims ----------------
#define T_STEPS   128
#define IN_DIM    512
#define C_INT     8
#define ISQ       16
#define DIMN      256
#define NCH       8
#define OUT_CH    16
#define EMB_OUT   2048          // C_INT*ISQ*ISQ

// ---------------- scratch (static device globals; no allocs) ----------------
__device__ float g_WT[IN_DIM * EMB_OUT];       // W_embed transposed: [k][o]
__device__ float g_v[T_STEPS * EMB_OUT];       // masked coarse activations
__device__ float g_Z[2][NCH * DIMN * DIMN];    // ping-pong reservoir state
__device__ int   g_flag[256 * 32];             // per-block step flags (128B stride)

// ---------------- fast tanh: 1 - 2/(e^{2x}+1) ----------------
__device__ __forceinline__ float ftanh(float s) {
    float e = __expf(s + s);
    return 1.f - __fdividef(2.f, e + 1.f);
}

// ---------------- W_embed transpose (tiled, conflict-free) ----------------
__global__ void k_transpose(const float* __restrict__ W) {
    __shared__ float tile[32][33];
    int ob = blockIdx.x * 32;
    int kb = blockIdx.y * 32;
    int tx = threadIdx.x, ty = threadIdx.y;
#pragma unroll
    for (int i = 0; i < 4; i++)
        tile[ty + 8 * i][tx] = W[(ob + ty + 8 * i) * IN_DIM + kb + tx];
    __syncthreads();
#pragma unroll
    for (int i = 0; i < 4; i++)
        g_WT[(kb + ty + 8 * i) * EMB_OUT + ob + tx] = tile[tx][ty + 8 * i];
}

// ---------------- embed GEMM: v[t][o] = (X[t,:]·W[o,:]) * mask_coarse ------
__global__ __launch_bounds__(256) void k_embed(const float* __restrict__ X,
                                               const float* __restrict__ maskc) {
    __shared__ float sX[16 * IN_DIM];
    int tt0 = blockIdx.x * 16;
    int ob  = blockIdx.y * 256;
    for (int idx = threadIdx.x; idx < 16 * IN_DIM; idx += 256)
        sX[idx] = X[(tt0 + (idx >> 9)) * IN_DIM + (idx & 511)];
    __syncthreads();

    int to = threadIdx.x & 63;
    int tg = threadIdx.x >> 6;
    float acc[4][4];
#pragma unroll
    for (int a = 0; a < 4; a++)
#pragma unroll
        for (int b = 0; b < 4; b++) acc[a][b] = 0.f;

    for (int k = 0; k < IN_DIM; k++) {
        float w[4];
#pragma unroll
        for (int oi = 0; oi < 4; oi++)
            w[oi] = g_WT[k * EMB_OUT + ob + to + 64 * oi];
#pragma unroll
        for (int ti = 0; ti < 4; ti++) {
            float xv = sX[(tg * 4 + ti) * IN_DIM + k];
#pragma unroll
            for (int oi = 0; oi < 4; oi++) acc[ti][oi] += xv * w[oi];
        }
    }
#pragma unroll
    for (int ti = 0; ti < 4; ti++)
#pragma unroll
        for (int oi = 0; oi < 4; oi++) {
            int t = tt0 + tg * 4 + ti;
            int o = ob + to + 64 * oi;
            g_v[t * EMB_OUT + o] = acc[ti][oi] * maskc[o & 255];
        }
}

// ---------------- init output with bias (d_out is poisoned) ----------------
__global__ void k_init_out(float* __restrict__ y, const float* __restrict__ b) {
    int idx = blockIdx.x * 256 + threadIdx.x;
    if (idx < T_STEPS * 1024) y[idx] = b[(idx >> 6) & 15];
}

// ---------------- zero initial state + flags ----------------
__global__ void k_zero() {
    int idx = blockIdx.x * 256 + threadIdx.x;
    if (idx < 256 * 32) g_flag[idx] = 0;
    if (idx < NCH * DIMN * DIMN) g_Z[0][idx] = 0.f;
}

// ---------------- persistent reservoir scan + fused readout ----------------
// grid = 256 blocks resident: block b -> channel c = b>>5, rows r0..r0+7
// thread = column x (0..255). Neighbor-only flag sync per step.
__global__ __launch_bounds__(256, 2) void k_scan(
    const float* __restrict__ maskf, const float* __restrict__ Wd,
    const float* __restrict__ w1g,  const float* __restrict__ w2g,
    const float* __restrict__ wog,  float* __restrict__ yout)
{
    const int blk = blockIdx.x;
    const int c   = blk >> 5;
    const int bb_ = blk & 31;
    const int r0  = bb_ << 3;
    const int tid = threadIdx.x;
    const int x   = tid;

    const int prev = (c << 5) | ((bb_ + 31) & 31);
    const int next = (c << 5) | ((bb_ + 1) & 31);

    __shared__ __align__(16) float s_tile[16][264];     // 16.9 KB
    __shared__ __align__(16) float s_wdecT[8 * 16 * 8]; // [al][b16][ci]  4 KB
    __shared__ __align__(16) float s_woutT[32 * 140];   // [xl][r*16+oc] 17.9 KB

    // ---- one-time staging: zero tile, load weights ----
    for (int idx = tid; idx < 16 * 264; idx += 256)
        ((float*)s_tile)[idx] = 0.f;
    const int a0 = r0 & 15;
    for (int idx = tid; idx < 1024; idx += 256) {
        int ci = idx & 7, b16 = (idx >> 3) & 15, al = idx >> 7;
        s_wdecT[idx] = Wd[ci * 2048 + c * 256 + (a0 + al) * 16 + b16];
    }
    for (int idx = tid; idx < 4096; idx += 256) {
        int oc = idx & 15, r = (idx >> 4) & 7, xl2 = idx >> 7;
        s_woutT[xl2 * 140 + r * 16 + oc] =
            wog[oc * 8192 + c * 1024 + ((r0 & 31) + r) * 32 + xl2];
    }
    float w1[9], w2[25], maskreg[8];
#pragma unroll
    for (int i = 0; i < 9; i++)  w1[i] = 0.9f * w1g[c * 9 + i];
#pragma unroll
    for (int i = 0; i < 25; i++) w2[i] = 0.1f * w2g[c * 25 + i];
#pragma unroll
    for (int r = 0; r < 8; r++)  maskreg[r] = maskf[(r0 + r) * 256 + x];

    const int jv  = x >> 4;
    const int b16 = x & 15;
    const int xl  = x & 31;
    const int iy  = r0 >> 5;
    const int jw  = x >> 5;
    const int ic  = r0 >> 4;
    const int sc  = x + 4;

    __syncthreads();

    for (int t = 0; t < T_STEPS; t++) {
        const float* __restrict__ Zc   = g_Z[t & 1] + c * 65536;
        float* __restrict__       Znew = g_Z[(t & 1) ^ 1] + c * 65536;

        // input activations for this step (independent of neighbors)
        float vr[8];
#pragma unroll
        for (int ci = 0; ci < 8; ci++)
            vr[ci] = __ldg(&g_v[t * EMB_OUT + ci * 256 + ic * 16 + jv]);

        if (t > 0) {
            // wait for ring neighbors to finish step t-1
            if (tid < 2) {
                volatile int* f = &g_flag[(tid == 0 ? prev : next) * 32];
                while (*f < t) { }
                __threadfence();
            }
            __syncthreads();

            // stage ONLY halo rows (r0-4..r0-1 and r0+8..r0+11)
            for (int idx = tid; idx < 8 * 264; idx += 256) {
                int rr  = idx / 264, sc2 = idx - rr * 264;
                int rrr = rr < 4 ? rr : rr + 8;
                int gr  = (r0 - 4 + rrr) & 255;
                int gc  = (sc2 - 4) & 255;
                s_tile[rrr][sc2] = __ldcg(&Zc[gr * 256 + gc]);
            }
            __syncthreads();
        }

        // ---- rolling depthwise convs: each tile row loaded once ----
        float acc[8];
#pragma unroll
        for (int r = 0; r < 8; r++) acc[r] = 0.f;

#pragma unroll
        for (int rr = 0; rr < 16; rr++) {
            float t0 = s_tile[rr][sc - 4];
            float t1 = s_tile[rr][sc - 2];
            float t2 = s_tile[rr][sc];
            float t3 = s_tile[rr][sc + 2];
            float t4 = s_tile[rr][sc + 4];
#pragma unroll
            for (int a = 0; a < 5; a++) {
                int r = rr - 2 * a;
                if (r >= 0 && r < 8)
                    acc[r] += t0 * w2[a * 5 + 0] + t1 * w2[a * 5 + 1]
                            + t2 * w2[a * 5 + 2] + t3 * w2[a * 5 + 3]
                            + t4 * w2[a * 5 + 4];
            }
            if (rr >= 3 && rr <= 12) {
                float u0 = s_tile[rr][sc - 1];
                float u2 = s_tile[rr][sc + 1];
#pragma unroll
                for (int a = 0; a < 3; a++) {
                    int r = rr - 3 - a;
                    if (r >= 0 && r < 8)
                        acc[r] += u0 * w1[a * 3 + 0] + t2 * w1[a * 3 + 1]
                                + u2 * w1[a * 3 + 2];
                }
            }
        }

        __syncthreads();   // all tile reads done before z overwrites own rows

        // ---- per-row: deconv input, tanh, smem+global store, readout ----
        float accro[16];
#pragma unroll
        for (int oc = 0; oc < 16; oc++) accro[oc] = 0.f;

#pragma unroll
        for (int r = 0; r < 8; r++) {
            const float4 wA = *(const float4*)&s_wdecT[r * 128 + b16 * 8];
            const float4 wB = *(const float4*)&s_wdecT[r * 128 + b16 * 8 + 4];
            float uv = vr[0] * wA.x + vr[1] * wA.y + vr[2] * wA.z + vr[3] * wA.w
                     + vr[4] * wB.x + vr[5] * wB.y + vr[6] * wB.z + vr[7] * wB.w;

            float z = ftanh(acc[r] + uv * maskreg[r]);

            // retain own row in smem (plus wrapped column halos)
            s_tile[4 + r][sc] = z;
            if (x < 4)    s_tile[4 + r][x + 260] = z;
            if (x >= 252) s_tile[4 + r][x - 252] = z;
            __stcg(&Znew[(r0 + r) * 256 + x], z);

            const float4 o0 = *(const float4*)&s_woutT[xl * 140 + r * 16 + 0];
            const float4 o1 = *(const float4*)&s_woutT[xl * 140 + r * 16 + 4];
            const float4 o2 = *(const float4*)&s_woutT[xl * 140 + r * 16 + 8];
            const float4 o3 = *(const float4*)&s_woutT[xl * 140 + r * 16 + 12];
            accro[0]  += z * o0.x;  accro[1]  += z * o0.y;
            accro[2]  += z * o0.z;  accro[3]  += z * o0.w;
            accro[4]  += z * o1.x;  accro[5]  += z * o1.y;
            accro[6]  += z * o1.z;  accro[7]  += z * o1.w;
            accro[8]  += z * o2.x;  accro[9]  += z * o2.y;
            accro[10] += z * o2.z;  accro[11] += z * o2.w;
            accro[12] += z * o3.x;  accro[13] += z * o3.y;
            accro[14] += z * o3.z;  accro[15] += z * o3.w;
        }

        // warp-level readout reduction (one 32-col band per warp)
#pragma unroll
        for (int oc = 0; oc < 16; oc++) {
            float v = accro[oc];
            v += __shfl_xor_sync(0xffffffffu, v, 16);
            v += __shfl_xor_sync(0xffffffffu, v, 8);
            v += __shfl_xor_sync(0xffffffffu, v, 4);
            v += __shfl_xor_sync(0xffffffffu, v, 2);
            v += __shfl_xor_sync(0xffffffffu, v, 1);
            if ((x & 31) == 0)
                atomicAdd(&yout[t * 1024 + oc * 64 + iy * 8 + jw], v);
        }

        __syncthreads();   // halo reads + z stores complete block-wide

        // publish: step t done (stores fenced, staging reads done)
        if (t < T_STEPS - 1 && tid == 0) {
            __threadfence();
            *(volatile int*)&g_flag[blk * 32] = t + 1;
        }
    }
}

// ---------------- launcher (graph-capturable, alloc-free) ----------------
extern "C" void kernel_launch(void* const* d_in, const int* in_sizes, int n_in,
                              void* d_out, int out_size)
{
    const float* X           = (const float*)d_in[0];  // [128,512]
    const float* W_embed     = (const float*)d_in[1];  // [2048,512]
    const float* mask_coarse = (const float*)d_in[2];  // [16,16]
    const float* mask_fine   = (const float*)d_in[3];  // [256,256]
    const float* W_deconv    = (const float*)d_in[4];  // [8,8,16,16]
    const float* w1          = (const float*)d_in[5];  // [8,1,3,3]
    const float* w2          = (const float*)d_in[6];  // [8,1,5,5]
    const float* w_out       = (const float*)d_in[7];  // [16,8,32,32]
    const float* b_out       = (const float*)d_in[8];  // [16]
    float* y = (float*)d_out;                          // [128,1024]

    k_transpose<<<dim3(64, 16), dim3(32, 8)>>>(W_embed);
    k_embed<<<dim3(8, 8), 256>>>(X, mask_coarse);
    k_init_out<<<512, 256>>>(y, b_out);
    k_zero<<<2048, 256>>>();
    k_scan<<<256, 256>>>(mask_fine, W_deconv, w1, w2, w_out, y);
}